// round 16
// baseline (speedup 1.0000x reference)
#include <cuda_runtime.h>
#include <cuda_fp16.h>
#include <stdint.h>

// ---------------- problem constants ----------------
#define KDIM 30000
#define MDIM 3200            // B*L
#define NDIM 1000            // Co
#define NPAD 1024
#define BDIM 32
#define CDIM 104
#define NPOOL 10
#define FCZ 10               // fc K-split (10000 = 10 * 1000)

// ---------------- GEMM tiling (fp16 mma; A fp32-in-smem w/ consumer cvt) ----
#define MT 128
#define NT 128
#define KB 64                             // k-values per stage
#define KSPLIT 10
#define KLEN (KDIM / KSPLIT)              // 3000 (16B-aligned in fp32 AND fp16)
#define ITERS ((KLEN + KB - 1) / KB)      // 47 (tail 56 = full 16B slots both sides)
#define SA 72                             // A row stride in floats  (LDS.64 conflict-free)
#define SB 72                             // B row stride in halves  (LDS.32 conflict-free)
#define A_BYTES (MT * SA * 4)             // 36864
#define B_BYTES (NT * SB * 2)             // 18432
#define STAGE_BYTES (A_BYTES + B_BYTES)   // 55296
#define SMEM_BYTES (2 * STAGE_BYTES)      // 110592 -> occ 2 with 128 threads

#define PART_FLOATS ((size_t)MDIM * NPAD) // 3,276,800

// ---------------- static scratch ----------------
__device__ __half g_wh[(size_t)NDIM * KDIM];   // fp16 conv_w (only w converted)
__device__ float g_part[PART_FLOATS];          // SINGLE accumulated conv output
__device__ float g_pool[BDIM * NDIM * NPOOL];
__device__ float g_ss[BDIM * 40];              // sum-of-squares partials (q,p)
__device__ float g_fcp[FCZ][BDIM][CDIM];       // fc K-split partials

// ---------------- helpers ----------------
static __device__ __forceinline__ uint32_t smem_u32(const void* p) {
    uint32_t a;
    asm("{ .reg .u64 t; cvta.to.shared.u64 t, %1; cvt.u32.u64 %0, t; }" : "=r"(a) : "l"(p));
    return a;
}
static __device__ __forceinline__ void cp_async16(uint32_t saddr, const void* gptr, uint32_t sz) {
    asm volatile("cp.async.cg.shared.global [%0], [%1], 16, %2;"
                 :: "r"(saddr), "l"(gptr), "r"(sz) : "memory");
}
static __device__ __forceinline__ void cp_commit() {
    asm volatile("cp.async.commit_group;" ::: "memory");
}
static __device__ __forceinline__ void cp_wait0() {
    asm volatile("cp.async.wait_group 0;" ::: "memory");
}
// fp32 pair from smem -> packed half2 register (LDS.64 + cvt.rn.f16x2)
static __device__ __forceinline__ uint32_t f2h2(const float* p) {
    float2 v = *(const float2*)p;
    __half2 h = __floats2half2_rn(v.x, v.y);
    return *(uint32_t*)&h;
}

#define MMA_F16(d, a, b)                                                           \
    asm volatile(                                                                  \
        "mma.sync.aligned.m16n8k16.row.col.f32.f16.f16.f32 "                       \
        "{%0,%1,%2,%3}, {%4,%5,%6,%7}, {%8,%9}, {%0,%1,%2,%3};"                    \
        : "+f"((d)[0]), "+f"((d)[1]), "+f"((d)[2]), "+f"((d)[3])                   \
        : "r"((a)[0]), "r"((a)[1]), "r"((a)[2]), "r"((a)[3]),                      \
          "r"((b)[0]), "r"((b)[1]))

// =====================================================================
// Kernel -1: zero the accumulator (13.1 MB, ~2 us) — required every
// launch for deterministic atomic accumulation.
// =====================================================================
__global__ void __launch_bounds__(256) zero_part_kernel() {
    const size_t n4 = PART_FLOATS / 4;
    size_t i = (size_t)blockIdx.x * blockDim.x + threadIdx.x;
    const size_t stride = (size_t)gridDim.x * blockDim.x;
    float4 z = make_float4(0.f, 0.f, 0.f, 0.f);
    for (; i < n4; i += stride) ((float4*)g_part)[i] = z;
}

// =====================================================================
// Kernel 0: fp32 -> fp16 (rn) for conv_w only (90 MB traffic, ~DRAM floor)
// =====================================================================
__global__ void __launch_bounds__(256) convert_w_kernel(const float* __restrict__ w,
                                                        __half* __restrict__ wh, int n8) {
    int i = blockIdx.x * blockDim.x + threadIdx.x;
    const int stride = gridDim.x * blockDim.x;
    for (; i < n8; i += stride) {
        float4 v0 = ((const float4*)w)[i * 2];
        float4 v1 = ((const float4*)w)[i * 2 + 1];
        __half2 h0 = __floats2half2_rn(v0.x, v0.y);
        __half2 h1 = __floats2half2_rn(v0.z, v0.w);
        __half2 h2 = __floats2half2_rn(v1.x, v1.y);
        __half2 h3 = __floats2half2_rn(v1.z, v1.w);
        uint4 o;
        o.x = *(uint32_t*)&h0; o.y = *(uint32_t*)&h1;
        o.z = *(uint32_t*)&h2; o.w = *(uint32_t*)&h3;
        ((uint4*)wh)[i] = o;
    }
}

// =====================================================================
// Kernel 1: GEMM, K split 10 ways; partial sums accumulated into the
// single g_part via atomicAdd (RED, no return). A: raw fp32 from x via
// cp.async, consumer-side cvt. B: fp16 scratch. CTA 128x128, 4 warps of
// 64x64, 2-stage pipeline, compile-time loop bounds (load-bearing).
// grid (25, 8, 10), block 128.
// =====================================================================
__global__ void __launch_bounds__(128, 2)
gemm_kernel(const float* __restrict__ x) {
    extern __shared__ char smem[];
    const int tid = threadIdx.x;
    const int wid = tid >> 5;
    const int lane = tid & 31;
    const int g = lane >> 2;        // groupID
    const int tig = lane & 3;       // thread in group
    const int wm = wid >> 1;        // 0..1
    const int wn = wid & 1;         // 0..1
    const int m0 = blockIdx.x * MT;
    const int n0 = blockIdx.y * NT;
    const int z = blockIdx.z;
    const uint32_t sbase = smem_u32(smem);

    // ---- A addressing: 16 items, row = (tid>>4) + 8u, slot = tid&15 (4 floats) ----
    const int slotA4 = (tid & 15) * 4;
    const float* baseA = x + (size_t)(m0 + (tid >> 4)) * KDIM + (size_t)z * KLEN + slotA4;
    const uint32_t soffA = (uint32_t)((tid >> 4) * (SA * 4) + (tid & 15) * 16);

    // ---- B addressing: 8 items, row = (tid>>3) + 16u, slot = tid&7 (8 halves) ----
    const int slotB8 = (tid & 7) * 8;
    const __half* gpB[8];
    uint32_t okB = 0;
    #pragma unroll
    for (int u = 0; u < 8; ++u) {
        int n = n0 + (tid >> 3) + 16 * u;
        if (n < NDIM) okB |= (1u << u);
        else n = NDIM - 1;
        gpB[u] = g_wh + (size_t)n * KDIM + (size_t)z * KLEN + slotB8;
    }
    const uint32_t soffB = (uint32_t)(A_BYTES + (tid >> 3) * (SB * 2) + (tid & 7) * 16);

    // tail = 56 k-values: A = 14 full float4 slots, B = 7 full 16B slots
    // -> sz is always 16 or 0 (cp.async src-size 0 zero-fills the line).
    #define ISSUE(it)                                                              \
        do {                                                                       \
            const int kb = (it) * KB;                                              \
            const int kleft = KLEN - kb;                                           \
            const uint32_t stb = sbase + ((it) & 1) * STAGE_BYTES;                 \
            const uint32_t szA = (slotA4 < kleft) ? 16u : 0u;                      \
            const float* pa = szA ? (baseA + kb) : baseA;  /* clamp OOB tail */    \
            _Pragma("unroll")                                                      \
            for (int u = 0; u < 16; ++u)                                           \
                cp_async16(stb + soffA + u * 2304u, pa + (size_t)u * 8 * KDIM, szA); \
            const uint32_t szB0 = (slotB8 < kleft) ? 16u : 0u;                     \
            _Pragma("unroll")                                                      \
            for (int u = 0; u < 8; ++u) {                                          \
                const uint32_t sz = ((okB >> u) & 1u) ? szB0 : 0u;                 \
                cp_async16(stb + soffB + u * 2304u, gpB[u] + kb, sz);              \
            }                                                                      \
        } while (0)

    // ---- prologue ----
    ISSUE(0); cp_commit();

    // ---- accumulators: warp tile 64x64 = 4x8 mma tiles ----
    float acc[4][8][4];
    #pragma unroll
    for (int mt = 0; mt < 4; ++mt)
        #pragma unroll
        for (int nt = 0; nt < 8; ++nt)
            #pragma unroll
            for (int r = 0; r < 4; ++r) acc[mt][nt][r] = 0.f;

    const int a_row0 = wm * 64 + g;
    const int b_row0 = wn * 64 + g;

    // ---- main loop (2-stage: wait0 -> sync -> issue(it+1) -> compute(it)) ----
    for (int it = 0; it < ITERS; ++it) {
        cp_wait0();
        __syncthreads();
        if (it + 1 < ITERS) { ISSUE(it + 1); }
        cp_commit();

        const float* As = (const float*)(smem + (it & 1) * STAGE_BYTES);
        const __half* Bs = (const __half*)(smem + (it & 1) * STAGE_BYTES + A_BYTES);

        #pragma unroll
        for (int ks = 0; ks < 4; ++ks) {
            const int kc = ks * 16 + 2 * tig;
            uint32_t af[4][4];
            #pragma unroll
            for (int mt = 0; mt < 4; ++mt) {
                const float* p = As + (a_row0 + mt * 16) * SA + kc;
                af[mt][0] = f2h2(p);
                af[mt][1] = f2h2(p + 8 * SA);
                af[mt][2] = f2h2(p + 8);
                af[mt][3] = f2h2(p + 8 * SA + 8);
            }
            uint32_t bf[8][2];
            #pragma unroll
            for (int nt = 0; nt < 8; ++nt) {
                const __half* p = Bs + (b_row0 + nt * 8) * SB + kc;
                bf[nt][0] = *(const uint32_t*)(p);
                bf[nt][1] = *(const uint32_t*)(p + 8);
            }
            #pragma unroll
            for (int mt = 0; mt < 4; ++mt)
                #pragma unroll
                for (int nt = 0; nt < 8; ++nt)
                    MMA_F16(acc[mt][nt], af[mt], bf[nt]);
        }
    }

    // ---- epilogue: accumulate into single g_part (RED.ADD, no return) ----
    #pragma unroll
    for (int mt = 0; mt < 4; ++mt) {
        const int r0 = m0 + wm * 64 + mt * 16 + g;
        #pragma unroll
        for (int nt = 0; nt < 8; ++nt) {
            const int c = n0 + wn * 64 + nt * 8 + 2 * tig;
            atomicAdd(&g_part[(size_t)r0 * NPAD + c],     acc[mt][nt][0]);
            atomicAdd(&g_part[(size_t)r0 * NPAD + c + 1], acc[mt][nt][1]);
            atomicAdd(&g_part[(size_t)(r0 + 8) * NPAD + c],     acc[mt][nt][2]);
            atomicAdd(&g_part[(size_t)(r0 + 8) * NPAD + c + 1], acc[mt][nt][3]);
        }
    }
    #undef ISSUE
}

// =====================================================================
// Kernel 2: bias + relu + avg-pool(10) + partial sum-of-squares
// grid (4, 32, 10): (channel quarter q, batch b, pool window p)
// Reads the single accumulated g_part (L2-resident, 13 MB).
// =====================================================================
__global__ void __launch_bounds__(256) pool_norm_kernel(const float* __restrict__ conv_b) {
    const int q = blockIdx.x;
    const int b = blockIdx.y;
    const int p = blockIdx.z;
    const int tid = threadIdx.x;
    __shared__ float red[256];

    float ss = 0.f;
    if (tid < 250) {
        const int o = q * 250 + tid;
        const float bias = conv_b[o];
        float acc = 0.f;
        #pragma unroll
        for (int i = 0; i < 10; ++i) {
            const size_t m = (size_t)(b * 100 + p * 10 + i) * NPAD + o;
            acc += fmaxf(g_part[m] + bias, 0.f);
        }
        const float v = acc * 0.1f;
        g_pool[(size_t)b * (NDIM * NPOOL) + o * NPOOL + p] = v;
        ss = v * v;
    }
    red[tid] = ss;
    __syncthreads();
    for (int st = 128; st > 0; st >>= 1) {
        if (tid < st) red[tid] += red[tid + st];
        __syncthreads();
    }
    if (tid == 0) g_ss[b * 40 + q * 10 + p] = red[0];
}

// =====================================================================
// Kernel 3a: fc partials — grid (104, 10), block 256 (8 warps).
// Block (c, z) covers K-slice [z*1000, (z+1)*1000) = 250 float4.
// =====================================================================
__global__ void __launch_bounds__(256) fc_partial_kernel(const float* __restrict__ fc_w) {
    const int c = blockIdx.x;
    const int z = blockIdx.y;
    const int wid = threadIdx.x >> 5;
    const int lane = threadIdx.x & 31;
    const float4* wrow = (const float4*)(fc_w + (size_t)c * (NDIM * NPOOL) + z * 1000);

    #pragma unroll
    for (int bb = 0; bb < 4; ++bb) {
        const int b = wid + bb * 8;
        const float4* pr = (const float4*)(g_pool + (size_t)b * (NDIM * NPOOL) + z * 1000);
        float acc = 0.f;
        #pragma unroll
        for (int k = lane; k < 250; k += 32) {
            float4 w4 = wrow[k];
            float4 p4 = pr[k];
            acc += w4.x * p4.x + w4.y * p4.y + w4.z * p4.z + w4.w * p4.w;
        }
        #pragma unroll
        for (int off = 16; off > 0; off >>= 1)
            acc += __shfl_xor_sync(0xFFFFFFFFu, acc, off);
        if (lane == 0) g_fcp[z][b][c] = acc;
    }
}

// =====================================================================
// Kernel 3b: finalize logits (3328 outputs)
// =====================================================================
__global__ void __launch_bounds__(256) fc_final_kernel(const float* __restrict__ fc_b,
                                                       float* __restrict__ out) {
    const int i = blockIdx.x * blockDim.x + threadIdx.x;
    if (i >= BDIM * CDIM) return;
    const int b = i / CDIM;
    const int c = i % CDIM;
    float ss = 0.f;
    #pragma unroll
    for (int j = 0; j < 40; ++j) ss += g_ss[b * 40 + j];
    float dot = 0.f;
    #pragma unroll
    for (int z = 0; z < FCZ; ++z) dot += g_fcp[z][b][c];
    out[i] = fc_b[c] + rsqrtf(1.0f + ss) * dot;
}

// =====================================================================
extern "C" void kernel_launch(void* const* d_in, const int* in_sizes, int n_in,
                              void* d_out, int out_size) {
    const float* x      = (const float*)d_in[0];  // [32,100,30000]
    const float* conv_w = (const float*)d_in[1];  // [1000,30000]
    const float* conv_b = (const float*)d_in[2];  // [1000]
    const float* fc_w   = (const float*)d_in[3];  // [104,10000]
    const float* fc_b   = (const float*)d_in[4];  // [104]
    float* out = (float*)d_out;                   // [32,104]

    static int configured = 0;
    if (!configured) {
        cudaFuncSetAttribute(gemm_kernel,
                             cudaFuncAttributeMaxDynamicSharedMemorySize, SMEM_BYTES);
        configured = 1;
    }

    __half* wh; cudaGetSymbolAddress((void**)&wh, g_wh);

    zero_part_kernel<<<1024, 256>>>();
    convert_w_kernel<<<1024, 256>>>(conv_w, wh, (NDIM * KDIM) / 8);
    gemm_kernel<<<dim3(MDIM / MT, 8, KSPLIT), 128, SMEM_BYTES>>>(x);
    pool_norm_kernel<<<dim3(4, BDIM, NPOOL), 256>>>(conv_b);
    fc_partial_kernel<<<dim3(CDIM, FCZ), 256>>>(fc_w);
    fc_final_kernel<<<(BDIM * CDIM + 255) / 256, 256>>>(fc_b, out);
}

// round 17
// speedup vs baseline: 1.0355x; 1.0355x over previous
#include <cuda_runtime.h>
#include <cuda_fp16.h>
#include <stdint.h>

// ---------------- problem constants ----------------
#define KDIM 30000
#define MDIM 3200            // B*L
#define NDIM 1000            // Co
#define NPAD 1024
#define BDIM 32
#define CDIM 104
#define NPOOL 10
#define FCZ 10               // fc K-split (10000 = 10 * 1000)

// ---------------- GEMM tiling (fp16 mma; A fp32-in-smem w/ consumer cvt) ----
#define MT 128
#define NT 128
#define KB 64                             // k-values per stage
#define KSPLIT 5
#define KLEN (KDIM / KSPLIT)              // 6000 (16B-aligned in fp32 AND fp16)
#define ITERS ((KLEN + KB - 1) / KB)      // 94 (tail 48 = full 16B slots both sides)
#define SA 72                             // A row stride in floats  (LDS.64 conflict-free)
#define SB 72                             // B row stride in halves  (LDS.32 conflict-free)
#define A_BYTES (MT * SA * 4)             // 36864
#define B_BYTES (NT * SB * 2)             // 18432
#define STAGE_BYTES (A_BYTES + B_BYTES)   // 55296
#define SMEM_BYTES (2 * STAGE_BYTES)      // 110592 -> occ 2 with 128 threads

#define PART_FLOATS ((size_t)MDIM * NPAD) // 3,276,800

// ---------------- static scratch ----------------
__device__ __half g_wh[(size_t)NDIM * KDIM];   // fp16 conv_w (only w converted)
__device__ float g_part[PART_FLOATS];          // SINGLE accumulated conv output
__device__ float g_pool[BDIM * NDIM * NPOOL];
__device__ float g_ss[BDIM * 40];              // sum-of-squares partials (q,p)
__device__ float g_fcp[FCZ][BDIM][CDIM];       // fc K-split partials

// ---------------- helpers ----------------
static __device__ __forceinline__ uint32_t smem_u32(const void* p) {
    uint32_t a;
    asm("{ .reg .u64 t; cvta.to.shared.u64 t, %1; cvt.u32.u64 %0, t; }" : "=r"(a) : "l"(p));
    return a;
}
static __device__ __forceinline__ void cp_async16(uint32_t saddr, const void* gptr, uint32_t sz) {
    asm volatile("cp.async.cg.shared.global [%0], [%1], 16, %2;"
                 :: "r"(saddr), "l"(gptr), "r"(sz) : "memory");
}
static __device__ __forceinline__ void cp_commit() {
    asm volatile("cp.async.commit_group;" ::: "memory");
}
static __device__ __forceinline__ void cp_wait0() {
    asm volatile("cp.async.wait_group 0;" ::: "memory");
}
// fp32 pair from smem -> packed half2 register (LDS.64 + cvt.rn.f16x2)
static __device__ __forceinline__ uint32_t f2h2(const float* p) {
    float2 v = *(const float2*)p;
    __half2 h = __floats2half2_rn(v.x, v.y);
    return *(uint32_t*)&h;
}

#define MMA_F16(d, a, b)                                                           \
    asm volatile(                                                                  \
        "mma.sync.aligned.m16n8k16.row.col.f32.f16.f16.f32 "                       \
        "{%0,%1,%2,%3}, {%4,%5,%6,%7}, {%8,%9}, {%0,%1,%2,%3};"                    \
        : "+f"((d)[0]), "+f"((d)[1]), "+f"((d)[2]), "+f"((d)[3])                   \
        : "r"((a)[0]), "r"((a)[1]), "r"((a)[2]), "r"((a)[3]),                      \
          "r"((b)[0]), "r"((b)[1]))

// =====================================================================
// Kernel -1: zero the accumulator (13.1 MB, ~2 us) — required every
// launch for deterministic atomic accumulation.
// =====================================================================
__global__ void __launch_bounds__(256) zero_part_kernel() {
    const size_t n4 = PART_FLOATS / 4;
    size_t i = (size_t)blockIdx.x * blockDim.x + threadIdx.x;
    const size_t stride = (size_t)gridDim.x * blockDim.x;
    float4 z = make_float4(0.f, 0.f, 0.f, 0.f);
    for (; i < n4; i += stride) ((float4*)g_part)[i] = z;
}

// =====================================================================
// Kernel 0: fp32 -> fp16 (rn) for conv_w only (90 MB traffic, ~DRAM floor)
// =====================================================================
__global__ void __launch_bounds__(256) convert_w_kernel(const float* __restrict__ w,
                                                        __half* __restrict__ wh, int n8) {
    int i = blockIdx.x * blockDim.x + threadIdx.x;
    const int stride = gridDim.x * blockDim.x;
    for (; i < n8; i += stride) {
        float4 v0 = ((const float4*)w)[i * 2];
        float4 v1 = ((const float4*)w)[i * 2 + 1];
        __half2 h0 = __floats2half2_rn(v0.x, v0.y);
        __half2 h1 = __floats2half2_rn(v0.z, v0.w);
        __half2 h2 = __floats2half2_rn(v1.x, v1.y);
        __half2 h3 = __floats2half2_rn(v1.z, v1.w);
        uint4 o;
        o.x = *(uint32_t*)&h0; o.y = *(uint32_t*)&h1;
        o.z = *(uint32_t*)&h2; o.w = *(uint32_t*)&h3;
        ((uint4*)wh)[i] = o;
    }
}

// =====================================================================
// Kernel 1: GEMM, K split 5 ways (measured-optimal quantum); partial
// sums accumulated into the single g_part via atomicAdd (RED, no
// return). A: raw fp32 from x via cp.async, consumer-side cvt.
// B: fp16 scratch. CTA 128x128, 4 warps of 64x64, 2-stage pipeline,
// compile-time loop bounds (load-bearing). grid (25, 8, 5), block 128.
// =====================================================================
__global__ void __launch_bounds__(128, 2)
gemm_kernel(const float* __restrict__ x) {
    extern __shared__ char smem[];
    const int tid = threadIdx.x;
    const int wid = tid >> 5;
    const int lane = tid & 31;
    const int g = lane >> 2;        // groupID
    const int tig = lane & 3;       // thread in group
    const int wm = wid >> 1;        // 0..1
    const int wn = wid & 1;         // 0..1
    const int m0 = blockIdx.x * MT;
    const int n0 = blockIdx.y * NT;
    const int z = blockIdx.z;
    const uint32_t sbase = smem_u32(smem);

    // ---- A addressing: 16 items, row = (tid>>4) + 8u, slot = tid&15 (4 floats) ----
    const int slotA4 = (tid & 15) * 4;
    const float* baseA = x + (size_t)(m0 + (tid >> 4)) * KDIM + (size_t)z * KLEN + slotA4;
    const uint32_t soffA = (uint32_t)((tid >> 4) * (SA * 4) + (tid & 15) * 16);

    // ---- B addressing: 8 items, row = (tid>>3) + 16u, slot = tid&7 (8 halves) ----
    const int slotB8 = (tid & 7) * 8;
    const __half* gpB[8];
    uint32_t okB = 0;
    #pragma unroll
    for (int u = 0; u < 8; ++u) {
        int n = n0 + (tid >> 3) + 16 * u;
        if (n < NDIM) okB |= (1u << u);
        else n = NDIM - 1;
        gpB[u] = g_wh + (size_t)n * KDIM + (size_t)z * KLEN + slotB8;
    }
    const uint32_t soffB = (uint32_t)(A_BYTES + (tid >> 3) * (SB * 2) + (tid & 7) * 16);

    // tail = 48 k-values: A = 12 full float4 slots, B = 6 full 16B slots
    // -> sz is always 16 or 0 (cp.async src-size 0 zero-fills the line).
    #define ISSUE(it)                                                              \
        do {                                                                       \
            const int kb = (it) * KB;                                              \
            const int kleft = KLEN - kb;                                           \
            const uint32_t stb = sbase + ((it) & 1) * STAGE_BYTES;                 \
            const uint32_t szA = (slotA4 < kleft) ? 16u : 0u;                      \
            const float* pa = szA ? (baseA + kb) : baseA;  /* clamp OOB tail */    \
            _Pragma("unroll")                                                      \
            for (int u = 0; u < 16; ++u)                                           \
                cp_async16(stb + soffA + u * 2304u, pa + (size_t)u * 8 * KDIM, szA); \
            const uint32_t szB0 = (slotB8 < kleft) ? 16u : 0u;                     \
            _Pragma("unroll")                                                      \
            for (int u = 0; u < 8; ++u) {                                          \
                const uint32_t sz = ((okB >> u) & 1u) ? szB0 : 0u;                 \
                cp_async16(stb + soffB + u * 2304u, gpB[u] + kb, sz);              \
            }                                                                      \
        } while (0)

    // ---- prologue ----
    ISSUE(0); cp_commit();

    // ---- accumulators: warp tile 64x64 = 4x8 mma tiles ----
    float acc[4][8][4];
    #pragma unroll
    for (int mt = 0; mt < 4; ++mt)
        #pragma unroll
        for (int nt = 0; nt < 8; ++nt)
            #pragma unroll
            for (int r = 0; r < 4; ++r) acc[mt][nt][r] = 0.f;

    const int a_row0 = wm * 64 + g;
    const int b_row0 = wn * 64 + g;

    // ---- main loop (2-stage: wait0 -> sync -> issue(it+1) -> compute(it)) ----
    for (int it = 0; it < ITERS; ++it) {
        cp_wait0();
        __syncthreads();
        if (it + 1 < ITERS) { ISSUE(it + 1); }
        cp_commit();

        const float* As = (const float*)(smem + (it & 1) * STAGE_BYTES);
        const __half* Bs = (const __half*)(smem + (it & 1) * STAGE_BYTES + A_BYTES);

        #pragma unroll
        for (int ks = 0; ks < 4; ++ks) {
            const int kc = ks * 16 + 2 * tig;
            uint32_t af[4][4];
            #pragma unroll
            for (int mt = 0; mt < 4; ++mt) {
                const float* p = As + (a_row0 + mt * 16) * SA + kc;
                af[mt][0] = f2h2(p);
                af[mt][1] = f2h2(p + 8 * SA);
                af[mt][2] = f2h2(p + 8);
                af[mt][3] = f2h2(p + 8 * SA + 8);
            }
            uint32_t bf[8][2];
            #pragma unroll
            for (int nt = 0; nt < 8; ++nt) {
                const __half* p = Bs + (b_row0 + nt * 8) * SB + kc;
                bf[nt][0] = *(const uint32_t*)(p);
                bf[nt][1] = *(const uint32_t*)(p + 8);
            }
            #pragma unroll
            for (int mt = 0; mt < 4; ++mt)
                #pragma unroll
                for (int nt = 0; nt < 8; ++nt)
                    MMA_F16(acc[mt][nt], af[mt], bf[nt]);
        }
    }

    // ---- epilogue: accumulate into single g_part (RED.ADD, no return) ----
    #pragma unroll
    for (int mt = 0; mt < 4; ++mt) {
        const int r0 = m0 + wm * 64 + mt * 16 + g;
        #pragma unroll
        for (int nt = 0; nt < 8; ++nt) {
            const int c = n0 + wn * 64 + nt * 8 + 2 * tig;
            atomicAdd(&g_part[(size_t)r0 * NPAD + c],     acc[mt][nt][0]);
            atomicAdd(&g_part[(size_t)r0 * NPAD + c + 1], acc[mt][nt][1]);
            atomicAdd(&g_part[(size_t)(r0 + 8) * NPAD + c],     acc[mt][nt][2]);
            atomicAdd(&g_part[(size_t)(r0 + 8) * NPAD + c + 1], acc[mt][nt][3]);
        }
    }
    #undef ISSUE
}

// =====================================================================
// Kernel 2: bias + relu + avg-pool(10) + partial sum-of-squares
// grid (4, 32, 10): (channel quarter q, batch b, pool window p)
// Reads the single accumulated g_part (13 MB, largely L2-resident).
// =====================================================================
__global__ void __launch_bounds__(256) pool_norm_kernel(const float* __restrict__ conv_b) {
    const int q = blockIdx.x;
    const int b = blockIdx.y;
    const int p = blockIdx.z;
    const int tid = threadIdx.x;
    __shared__ float red[256];

    float ss = 0.f;
    if (tid < 250) {
        const int o = q * 250 + tid;
        const float bias = conv_b[o];
        float acc = 0.f;
        #pragma unroll
        for (int i = 0; i < 10; ++i) {
            const size_t m = (size_t)(b * 100 + p * 10 + i) * NPAD + o;
            acc += fmaxf(g_part[m] + bias, 0.f);
        }
        const float v = acc * 0.1f;
        g_pool[(size_t)b * (NDIM * NPOOL) + o * NPOOL + p] = v;
        ss = v * v;
    }
    red[tid] = ss;
    __syncthreads();
    for (int st = 128; st > 0; st >>= 1) {
        if (tid < st) red[tid] += red[tid + st];
        __syncthreads();
    }
    if (tid == 0) g_ss[b * 40 + q * 10 + p] = red[0];
}

// =====================================================================
// Kernel 3a: fc partials — grid (104, 10), block 256 (8 warps).
// Block (c, z) covers K-slice [z*1000, (z+1)*1000) = 250 float4.
// =====================================================================
__global__ void __launch_bounds__(256) fc_partial_kernel(const float* __restrict__ fc_w) {
    const int c = blockIdx.x;
    const int z = blockIdx.y;
    const int wid = threadIdx.x >> 5;
    const int lane = threadIdx.x & 31;
    const float4* wrow = (const float4*)(fc_w + (size_t)c * (NDIM * NPOOL) + z * 1000);

    #pragma unroll
    for (int bb = 0; bb < 4; ++bb) {
        const int b = wid + bb * 8;
        const float4* pr = (const float4*)(g_pool + (size_t)b * (NDIM * NPOOL) + z * 1000);
        float acc = 0.f;
        #pragma unroll
        for (int k = lane; k < 250; k += 32) {
            float4 w4 = wrow[k];
            float4 p4 = pr[k];
            acc += w4.x * p4.x + w4.y * p4.y + w4.z * p4.z + w4.w * p4.w;
        }
        #pragma unroll
        for (int off = 16; off > 0; off >>= 1)
            acc += __shfl_xor_sync(0xFFFFFFFFu, acc, off);
        if (lane == 0) g_fcp[z][b][c] = acc;
    }
}

// =====================================================================
// Kernel 3b: finalize logits (3328 outputs)
// =====================================================================
__global__ void __launch_bounds__(256) fc_final_kernel(const float* __restrict__ fc_b,
                                                       float* __restrict__ out) {
    const int i = blockIdx.x * blockDim.x + threadIdx.x;
    if (i >= BDIM * CDIM) return;
    const int b = i / CDIM;
    const int c = i % CDIM;
    float ss = 0.f;
    #pragma unroll
    for (int j = 0; j < 40; ++j) ss += g_ss[b * 40 + j];
    float dot = 0.f;
    #pragma unroll
    for (int z = 0; z < FCZ; ++z) dot += g_fcp[z][b][c];
    out[i] = fc_b[c] + rsqrtf(1.0f + ss) * dot;
}

// =====================================================================
extern "C" void kernel_launch(void* const* d_in, const int* in_sizes, int n_in,
                              void* d_out, int out_size) {
    const float* x      = (const float*)d_in[0];  // [32,100,30000]
    const float* conv_w = (const float*)d_in[1];  // [1000,30000]
    const float* conv_b = (const float*)d_in[2];  // [1000]
    const float* fc_w   = (const float*)d_in[3];  // [104,10000]
    const float* fc_b   = (const float*)d_in[4];  // [104]
    float* out = (float*)d_out;                   // [32,104]

    static int configured = 0;
    if (!configured) {
        cudaFuncSetAttribute(gemm_kernel,
                             cudaFuncAttributeMaxDynamicSharedMemorySize, SMEM_BYTES);
        configured = 1;
    }

    __half* wh; cudaGetSymbolAddress((void**)&wh, g_wh);

    zero_part_kernel<<<1024, 256>>>();
    convert_w_kernel<<<1024, 256>>>(conv_w, wh, (NDIM * KDIM) / 8);
    gemm_kernel<<<dim3(MDIM / MT, 8, KSPLIT), 128, SMEM_BYTES>>>(x);
    pool_norm_kernel<<<dim3(4, BDIM, NPOOL), 256>>>(conv_b);
    fc_partial_kernel<<<dim3(CDIM, FCZ), 256>>>(fc_w);
    fc_final_kernel<<<(BDIM * CDIM + 255) / 256, 256>>>(fc_b, out);
}